// round 15
// baseline (speedup 1.0000x reference)
#include <cuda_runtime.h>
#include <cuda_fp16.h>
#include <cstdint>
#include <math.h>

#define MAXN 100000
typedef unsigned long long u64;
typedef unsigned int u32;

// ---------------- scratch (device globals) ----------------------------------
__device__ int   g_is64;
__device__ __align__(16) __half g_yp[MAXN * 32];    // fp16: x @ W1p[0:64]
__device__ __align__(16) __half g_yn[MAXN * 32];    // fp16: x @ W1n[0:64]
__device__ float g_sxp[MAXN * 32];                  // fp32: x @ W1p[64:128] + b1p
__device__ float g_sxn[MAXN * 32];                  // fp32: x @ W1n[64:128] + b1n
__device__ __align__(16) __half g_apsum[MAXN * 32]; // fp16 seg_sum(yp, pos)
__device__ __align__(16) __half g_ansum[MAXN * 32]; // fp16 seg_sum(yn, neg)
__device__ float g_cntp[MAXN];
__device__ float g_cntn[MAXN];
__device__ __align__(16) __half g_zc[MAXN * 64];    // fp16 [zp | zn], 128B rows
__device__ __align__(16) __half g_sump[MAXN * 64];  // fp16 seg_sum(zc, pos)
__device__ __align__(16) __half g_sumn[MAXN * 64];  // fp16 seg_sum(zc, neg)

// ---------------- helpers ---------------------------------------------------
__device__ __forceinline__ void red_add_h8(void* addr, uint4 v) {
    asm volatile("red.global.add.noftz.v4.f16x2 [%0], {%1, %2, %3, %4};"
                 :: "l"(addr), "r"(v.x), "r"(v.y), "r"(v.z), "r"(v.w)
                 : "memory");
}
__device__ __forceinline__ int load_idx(const void* ei, long long pos, int is64) {
    if (is64) return (int)__ldg((const long long*)ei + pos);
    return __ldg((const int*)ei + pos);
}
__device__ __forceinline__ u64 pack2(float s) {
    u64 r; asm("mov.b64 %0, {%1, %1};" : "=l"(r) : "f"(s)); return r;
}
__device__ __forceinline__ void fma2(u64& d, u64 a, u64 b) {
    asm("fma.rn.f32x2 %0, %1, %2, %0;" : "+l"(d) : "l"(a), "l"(b));
}
__device__ __forceinline__ float2 unpack2(u64 v) {
    float2 r; asm("mov.b64 {%0, %1}, %2;" : "=f"(r.x), "=f"(r.y) : "l"(v)); return r;
}
__device__ __forceinline__ void row_fma2n(u64 a0[16], u64 a1[16], const float* Ws,
                                          int k, u64 s0, u64 s1) {
    const u64* w = (const u64*)(Ws + k * 32);
#pragma unroll
    for (int j = 0; j < 16; j++) {
        u64 ww = w[j];
        fma2(a0[j], s0, ww);
        fma2(a1[j], s1, ww);
    }
}
__device__ __forceinline__ float2 h2f(u32 w) {
    __half2 h = *reinterpret_cast<__half2*>(&w);
    return __half22float2(h);
}
__device__ __forceinline__ u32 f2h(float a, float b) {
    __half2 h = __floats2half2_rn(a, b);
    return *reinterpret_cast<u32*>(&h);
}

// ---------------- projY + zero + dtype: y(fp16) = x@W1[0:64] ------------------
__global__ void projYZ(const unsigned int* __restrict__ p, const float* __restrict__ x,
                       const float* __restrict__ W1p, const float* __restrict__ W1n,
                       int n) {
    __shared__ float Wp[64 * 32];
    __shared__ float Wn[64 * 32];
    for (int t = threadIdx.x; t < 64 * 32; t += blockDim.x) { Wp[t] = W1p[t]; Wn[t] = W1n[t]; }
    if (blockIdx.x == 0 && threadIdx.x == 0) {
        int is64 = 1;
        for (int i = 1; i < 256; i += 2)
            if (p[i] != 0u) { is64 = 0; break; }
        g_is64 = is64;
    }
    __syncthreads();
    int sign = threadIdx.x >> 7;
    int i0 = blockIdx.x * 256 + (threadIdx.x & 127);
    int i1 = i0 + 128;
    if (i0 >= n) return;
    bool v1 = (i1 < n);
    int i1c = v1 ? i1 : i0;

    // zero scatter targets for this thread's nodes (per sign)
    {
        const uint4 z = make_uint4(0, 0, 0, 0);
        __half* asum = sign ? g_ansum : g_apsum;
        __half* lsum = sign ? g_sumn : g_sump;
        float* cnt = sign ? g_cntn : g_cntp;
        uint4* a0z = (uint4*)(asum + (size_t)i0 * 32);
        uint4* s0z = (uint4*)(lsum + (size_t)i0 * 64);
#pragma unroll
        for (int q = 0; q < 4; q++) a0z[q] = z;
#pragma unroll
        for (int q = 0; q < 8; q++) s0z[q] = z;
        cnt[i0] = 0.f;
        if (v1) {
            uint4* a1z = (uint4*)(asum + (size_t)i1 * 32);
            uint4* s1z = (uint4*)(lsum + (size_t)i1 * 64);
#pragma unroll
            for (int q = 0; q < 4; q++) a1z[q] = z;
#pragma unroll
            for (int q = 0; q < 8; q++) s1z[q] = z;
            cnt[i1] = 0.f;
        }
    }

    const float* Ws = sign ? Wn : Wp;
    const float4* x0 = (const float4*)x + (size_t)i0 * 16;
    const float4* x1 = (const float4*)x + (size_t)i1c * 16;

    u64 a0[16], a1[16];
#pragma unroll
    for (int j = 0; j < 16; j++) { a0[j] = 0ULL; a1[j] = 0ULL; }
#pragma unroll 2
    for (int kk = 0; kk < 16; kk++) {
        float4 pv = x0[kk];
        float4 qv = x1[kk];
        int k = kk * 4;
        row_fma2n(a0, a1, Ws, k + 0, pack2(pv.x), pack2(qv.x));
        row_fma2n(a0, a1, Ws, k + 1, pack2(pv.y), pack2(qv.y));
        row_fma2n(a0, a1, Ws, k + 2, pack2(pv.z), pack2(qv.z));
        row_fma2n(a0, a1, Ws, k + 3, pack2(pv.w), pack2(qv.w));
    }
    __half* yb = sign ? g_yn : g_yp;
    uint4* yo0 = (uint4*)(yb + (size_t)i0 * 32);
#pragma unroll
    for (int q = 0; q < 4; q++) {
        float2 f0 = unpack2(a0[q * 4 + 0]), f1 = unpack2(a0[q * 4 + 1]);
        float2 f2 = unpack2(a0[q * 4 + 2]), f3 = unpack2(a0[q * 4 + 3]);
        yo0[q] = make_uint4(f2h(f0.x, f0.y), f2h(f1.x, f1.y), f2h(f2.x, f2.y), f2h(f3.x, f3.y));
    }
    if (v1) {
        uint4* yo1 = (uint4*)(yb + (size_t)i1 * 32);
#pragma unroll
        for (int q = 0; q < 4; q++) {
            float2 f0 = unpack2(a1[q * 4 + 0]), f1 = unpack2(a1[q * 4 + 1]);
            float2 f2 = unpack2(a1[q * 4 + 2]), f3 = unpack2(a1[q * 4 + 3]);
            yo1[q] = make_uint4(f2h(f0.x, f0.y), f2h(f1.x, f1.y), f2h(f2.x, f2.y), f2h(f3.x, f3.y));
        }
    }
}

// ---------------- fused: sx-GEMM blocks + layer-1 edge scatter blocks --------
// blocks [0, nbg): sx = x@W1[64:128]+b (fp32) ; blocks [nbg, nbg+4736): edge scatter
__device__ __forceinline__ void edge1_body(const void* pe, const void* ne, int E,
                                           int is64, long long item) {
    long long e2 = item >> 2;
    int c = (int)(item & 3);
    bool pos = e2 < E;
    const void* ei = pos ? pe : ne;
    long long e = pos ? e2 : e2 - E;
    const __half* y = pos ? g_yp : g_yn;
    __half* sum = pos ? g_apsum : g_ansum;
    float* cnt = pos ? g_cntp : g_cntn;
    int s = load_idx(ei, e, is64);
    int d = load_idx(ei, (long long)E + e, is64);
    uint4 v = __ldg((const uint4*)y + (size_t)s * 4 + c);
    red_add_h8((uint4*)sum + (size_t)d * 4 + c, v);
    if (c == 0) atomicAdd(cnt + d, 1.0f);
}

__global__ void edge1sx(const void* __restrict__ pe, const void* __restrict__ ne, int E,
                        const float* __restrict__ x,
                        const float* __restrict__ W1p, const float* __restrict__ b1p,
                        const float* __restrict__ W1n, const float* __restrict__ b1n,
                        int n, int nbg) {
    __shared__ float Wsm[2][64 * 32];
    if ((int)blockIdx.x < nbg) {
        // ---- sx GEMM role ----
        for (int t = threadIdx.x; t < 64 * 32; t += blockDim.x) {
            Wsm[0][t] = W1p[64 * 32 + t];
            Wsm[1][t] = W1n[64 * 32 + t];
        }
        __syncthreads();
        int sign = threadIdx.x >> 7;
        int i0 = blockIdx.x * 256 + (threadIdx.x & 127);
        int i1 = i0 + 128;
        if (i0 >= n) return;
        bool v1 = (i1 < n);
        int i1c = v1 ? i1 : i0;

        const float* Ws = Wsm[sign];
        const float4* x0 = (const float4*)x + (size_t)i0 * 16;
        const float4* x1 = (const float4*)x + (size_t)i1c * 16;

        u64 a0[16], a1[16];
#pragma unroll
        for (int j = 0; j < 16; j++) { a0[j] = 0ULL; a1[j] = 0ULL; }
#pragma unroll 2
        for (int kk = 0; kk < 16; kk++) {
            float4 pv = x0[kk];
            float4 qv = x1[kk];
            int k = kk * 4;
            row_fma2n(a0, a1, Ws, k + 0, pack2(pv.x), pack2(qv.x));
            row_fma2n(a0, a1, Ws, k + 1, pack2(pv.y), pack2(qv.y));
            row_fma2n(a0, a1, Ws, k + 2, pack2(pv.z), pack2(qv.z));
            row_fma2n(a0, a1, Ws, k + 3, pack2(pv.w), pack2(qv.w));
        }
        const float2* bb = (const float2*)(sign ? b1n : b1p);
        float* sb = sign ? g_sxn : g_sxp;
        float2* so0 = (float2*)(sb + (size_t)i0 * 32);
        float2* so1 = (float2*)(sb + (size_t)i1 * 32);
#pragma unroll
        for (int j = 0; j < 16; j++) {
            float2 b = __ldg(bb + j);
            float2 f = unpack2(a0[j]);
            so0[j] = make_float2(f.x + b.x, f.y + b.y);
            if (v1) {
                f = unpack2(a1[j]);
                so1[j] = make_float2(f.x + b.x, f.y + b.y);
            }
        }
    } else {
        // ---- edge scatter role ----
        const int is64 = g_is64;
        int nb = gridDim.x - nbg;
        long long total = (long long)E * 8;  // 2E edges * 4 items (16B each)
        long long stride = (long long)nb * blockDim.x;
        long long item = (long long)((int)blockIdx.x - nbg) * blockDim.x + threadIdx.x;
        for (; item + stride < total; item += 2 * stride) {
            edge1_body(pe, ne, E, is64, item);
            edge1_body(pe, ne, E, is64, item + stride);
        }
        if (item < total) edge1_body(pe, ne, E, is64, item);
    }
}

// ---------------- layer-1 activation: zc = tanh(sum*inv + sx) (fp16 out) -----
__global__ void node1b(int n) {
    int t = blockIdx.x * blockDim.x + threadIdx.x;
    int d = t >> 2, c = t & 3;
    if (d >= n) return;
    float invp = 1.f / fmaxf(g_cntp[d], 1.f);
    float invn = 1.f / fmaxf(g_cntn[d], 1.f);

    {
        uint4 a = __ldg((const uint4*)g_apsum + (size_t)d * 4 + c);
        float4 s0 = __ldg((const float4*)g_sxp + (size_t)d * 8 + c * 2);
        float4 s1 = __ldg((const float4*)g_sxp + (size_t)d * 8 + c * 2 + 1);
        float2 f0 = h2f(a.x), f1 = h2f(a.y), f2 = h2f(a.z), f3 = h2f(a.w);
        uint4 o;
        o.x = f2h(tanhf(fmaf(f0.x, invp, s0.x)), tanhf(fmaf(f0.y, invp, s0.y)));
        o.y = f2h(tanhf(fmaf(f1.x, invp, s0.z)), tanhf(fmaf(f1.y, invp, s0.w)));
        o.z = f2h(tanhf(fmaf(f2.x, invp, s1.x)), tanhf(fmaf(f2.y, invp, s1.y)));
        o.w = f2h(tanhf(fmaf(f3.x, invp, s1.z)), tanhf(fmaf(f3.y, invp, s1.w)));
        ((uint4*)g_zc)[(size_t)d * 8 + c] = o;
    }
    {
        uint4 a = __ldg((const uint4*)g_ansum + (size_t)d * 4 + c);
        float4 s0 = __ldg((const float4*)g_sxn + (size_t)d * 8 + c * 2);
        float4 s1 = __ldg((const float4*)g_sxn + (size_t)d * 8 + c * 2 + 1);
        float2 f0 = h2f(a.x), f1 = h2f(a.y), f2 = h2f(a.z), f3 = h2f(a.w);
        uint4 o;
        o.x = f2h(tanhf(fmaf(f0.x, invn, s0.x)), tanhf(fmaf(f0.y, invn, s0.y)));
        o.y = f2h(tanhf(fmaf(f1.x, invn, s0.z)), tanhf(fmaf(f1.y, invn, s0.w)));
        o.z = f2h(tanhf(fmaf(f2.x, invn, s1.x)), tanhf(fmaf(f2.y, invn, s1.y)));
        o.w = f2h(tanhf(fmaf(f3.x, invn, s1.z)), tanhf(fmaf(f3.y, invn, s1.w)));
        ((uint4*)g_zc)[(size_t)d * 8 + 4 + c] = o;
    }
}

// ---------------- layer-2 edge scatter (fp16 zc rows, 128B) ------------------
__device__ __forceinline__ void edge2_body(const void* pe, const void* ne, int E,
                                           int is64, long long item) {
    long long e2 = item >> 3;
    int c = (int)(item & 7);
    bool pos = e2 < E;
    const void* ei = pos ? pe : ne;
    long long e = pos ? e2 : e2 - E;
    __half* sum = pos ? g_sump : g_sumn;
    int s = load_idx(ei, e, is64);
    int d = load_idx(ei, (long long)E + e, is64);
    uint4 v = __ldg((const uint4*)g_zc + (size_t)s * 8 + c);
    red_add_h8((uint4*)sum + (size_t)d * 8 + c, v);
}

__global__ void edge2(const void* __restrict__ pe, const void* __restrict__ ne, int E) {
    const int is64 = g_is64;
    long long total = (long long)E * 16;  // 2E edges * 8 items (16B each)
    long long stride = (long long)gridDim.x * blockDim.x;
    long long item = (long long)blockIdx.x * blockDim.x + threadIdx.x;
    for (; item + stride < total; item += 2 * stride) {
        edge2_body(pe, ne, E, is64, item);
        edge2_body(pe, ne, E, is64, item + stride);
    }
    if (item < total) edge2_body(pe, ne, E, is64, item);
}

// ---------------- layer-2 dual-node GEMM section ------------------------------
__device__ __forceinline__ void gemm_sec2n(u64 a0[16], u64 a1[16], const float* Ws,
                                           int kbase, const uint4* s0p, const uint4* s1p,
                                           float sc0, float sc1) {
#pragma unroll
    for (int q = 0; q < 4; q++) {
        uint4 u0 = __ldg(s0p + q);
        uint4 u1 = __ldg(s1p + q);
        int k = kbase + q * 8;
        float2 f0, f1;
        f0 = h2f(u0.x); f1 = h2f(u1.x);
        row_fma2n(a0, a1, Ws, k + 0, pack2(f0.x * sc0), pack2(f1.x * sc1));
        row_fma2n(a0, a1, Ws, k + 1, pack2(f0.y * sc0), pack2(f1.y * sc1));
        f0 = h2f(u0.y); f1 = h2f(u1.y);
        row_fma2n(a0, a1, Ws, k + 2, pack2(f0.x * sc0), pack2(f1.x * sc1));
        row_fma2n(a0, a1, Ws, k + 3, pack2(f0.y * sc0), pack2(f1.y * sc1));
        f0 = h2f(u0.z); f1 = h2f(u1.z);
        row_fma2n(a0, a1, Ws, k + 4, pack2(f0.x * sc0), pack2(f1.x * sc1));
        row_fma2n(a0, a1, Ws, k + 5, pack2(f0.y * sc0), pack2(f1.y * sc1));
        f0 = h2f(u0.w); f1 = h2f(u1.w);
        row_fma2n(a0, a1, Ws, k + 6, pack2(f0.x * sc0), pack2(f1.x * sc1));
        row_fma2n(a0, a1, Ws, k + 7, pack2(f0.y * sc0), pack2(f1.y * sc1));
    }
}

// ---------------- layer-2 node GEMM -> output (2-node blocked) ----------------
__global__ void node_l2(const float* __restrict__ W2p, const float* __restrict__ b2p,
                        const float* __restrict__ W2n, const float* __restrict__ b2n,
                        float* __restrict__ out, int n) {
    __shared__ float Wp[96 * 32];
    __shared__ float Wn[96 * 32];
    for (int t = threadIdx.x; t < 96 * 32; t += blockDim.x) { Wp[t] = W2p[t]; Wn[t] = W2n[t]; }
    __syncthreads();
    int sign = threadIdx.x >> 7;
    int i0 = blockIdx.x * 256 + (threadIdx.x & 127);
    int i1 = i0 + 128;
    if (i0 >= n) return;
    bool v1 = (i1 < n);
    int i1c = v1 ? i1 : i0;

    float invp0 = 1.f / fmaxf(g_cntp[i0], 1.f);
    float invn0 = 1.f / fmaxf(g_cntn[i0], 1.f);
    float invp1 = 1.f / fmaxf(g_cntp[i1c], 1.f);
    float invn1 = 1.f / fmaxf(g_cntn[i1c], 1.f);

    int ho = sign ? 4 : 0;
    const uint4* s0a = (const uint4*)g_sump + (size_t)i0 * 8 + ho;
    const uint4* s1a = (const uint4*)g_sumn + (size_t)i0 * 8 + (4 - ho);
    const uint4* s2a = (const uint4*)g_zc   + (size_t)i0 * 8 + ho;
    const uint4* s0b = (const uint4*)g_sump + (size_t)i1c * 8 + ho;
    const uint4* s1b = (const uint4*)g_sumn + (size_t)i1c * 8 + (4 - ho);
    const uint4* s2b = (const uint4*)g_zc   + (size_t)i1c * 8 + ho;
    const float* Ws = sign ? Wn : Wp;

    u64 a0[16], a1[16];
#pragma unroll
    for (int j = 0; j < 16; j++) { a0[j] = 0ULL; a1[j] = 0ULL; }
    gemm_sec2n(a0, a1, Ws, 0,  s0a, s0b, invp0, invp1);
    gemm_sec2n(a0, a1, Ws, 32, s1a, s1b, invn0, invn1);
    gemm_sec2n(a0, a1, Ws, 64, s2a, s2b, 1.0f, 1.0f);

    const float2* bb = (const float2*)(sign ? b2n : b2p);
    float2* o0 = (float2*)(out + (size_t)i0 * 64 + (sign ? 32 : 0));
    float2* o1 = (float2*)(out + (size_t)i1 * 64 + (sign ? 32 : 0));
#pragma unroll
    for (int j = 0; j < 16; j++) {
        float2 b = __ldg(bb + j);
        float2 f = unpack2(a0[j]);
        o0[j] = make_float2(tanhf(f.x + b.x), tanhf(f.y + b.y));
        if (v1) {
            f = unpack2(a1[j]);
            o1[j] = make_float2(tanhf(f.x + b.x), tanhf(f.y + b.y));
        }
    }
}

// ---------------- launch ------------------------------------------------------
extern "C" void kernel_launch(void* const* d_in, const int* in_sizes, int n_in,
                              void* d_out, int out_size) {
    const float* x   = (const float*)d_in[0];
    const float* W1p = (const float*)d_in[1];
    const float* b1p = (const float*)d_in[2];
    const float* W1n = (const float*)d_in[3];
    const float* b1n = (const float*)d_in[4];
    const float* W2p = (const float*)d_in[5];
    const float* b2p = (const float*)d_in[6];
    const float* W2n = (const float*)d_in[7];
    const float* b2n = (const float*)d_in[8];
    const void* pe = d_in[9];
    const void* ne = d_in[10];

    int n = in_sizes[0] / 64;
    int E = in_sizes[9] / 2;
    float* out = (float*)d_out;
    int nbg = (n + 255) / 256;  // sx-GEMM blocks inside edge1sx

    projYZ<<<(n + 255) / 256, 256>>>((const unsigned int*)pe, x, W1p, W1n, n);
    edge1sx<<<nbg + 4736, 256>>>(pe, ne, E, x, W1p, b1p, W1n, b1n, n, nbg);
    node1b<<<(n * 4 + 255) / 256, 256>>>(n);
    edge2<<<4736, 256>>>(pe, ne, E);
    node_l2<<<(n + 255) / 256, 256>>>(W2p, b2p, W2n, b2n, out, n);
}

// round 16
// speedup vs baseline: 1.1615x; 1.1615x over previous
#include <cuda_runtime.h>
#include <cuda_fp16.h>
#include <cstdint>
#include <math.h>

#define MAXN 100000
typedef unsigned long long u64;
typedef unsigned int u32;

// ---------------- scratch (device globals) ----------------------------------
__device__ int   g_is64;
__device__ __align__(16) __half g_yp[MAXN * 32];    // fp16: x @ W1p[0:64]
__device__ __align__(16) __half g_yn[MAXN * 32];    // fp16: x @ W1n[0:64]
__device__ __align__(16) __half g_apsum[MAXN * 32]; // fp16 seg_sum(yp, pos)
__device__ __align__(16) __half g_ansum[MAXN * 32]; // fp16 seg_sum(yn, neg)
__device__ float g_cntp[MAXN];
__device__ float g_cntn[MAXN];
__device__ __align__(16) __half g_zc[MAXN * 64];    // fp16 [zp | zn], 128B rows
__device__ __align__(16) __half g_sump[MAXN * 64];  // fp16 seg_sum(zc, pos)
__device__ __align__(16) __half g_sumn[MAXN * 64];  // fp16 seg_sum(zc, neg)

// ---------------- helpers ---------------------------------------------------
__device__ __forceinline__ void red_add_h8(void* addr, uint4 v) {
    asm volatile("red.global.add.noftz.v4.f16x2 [%0], {%1, %2, %3, %4};"
                 :: "l"(addr), "r"(v.x), "r"(v.y), "r"(v.z), "r"(v.w)
                 : "memory");
}
__device__ __forceinline__ int load_idx(const void* ei, long long pos, int is64) {
    if (is64) return (int)__ldg((const long long*)ei + pos);
    return __ldg((const int*)ei + pos);
}
__device__ __forceinline__ u64 pack2(float s) {
    u64 r; asm("mov.b64 %0, {%1, %1};" : "=l"(r) : "f"(s)); return r;
}
__device__ __forceinline__ void fma2(u64& d, u64 a, u64 b) {
    asm("fma.rn.f32x2 %0, %1, %2, %0;" : "+l"(d) : "l"(a), "l"(b));
}
__device__ __forceinline__ float2 unpack2(u64 v) {
    float2 r; asm("mov.b64 {%0, %1}, %2;" : "=f"(r.x), "=f"(r.y) : "l"(v)); return r;
}
// dual-node row FMA: weight row loaded from shared ONCE, used for both nodes
__device__ __forceinline__ void row_fma2n(u64 a0[16], u64 a1[16], const float* Ws,
                                          int k, u64 s0, u64 s1) {
    const u64* w = (const u64*)(Ws + k * 32);
#pragma unroll
    for (int j = 0; j < 16; j++) {
        u64 ww = w[j];
        fma2(a0[j], s0, ww);
        fma2(a1[j], s1, ww);
    }
}
__device__ __forceinline__ float2 h2f(u32 w) {
    __half2 h = *reinterpret_cast<__half2*>(&w);
    return __half22float2(h);
}
__device__ __forceinline__ u32 f2h(float a, float b) {
    __half2 h = __floats2half2_rn(a, b);
    return *reinterpret_cast<u32*>(&h);
}

// ---------------- projY + zero + dtype: y(fp16) = x@W1[0:64] ------------------
// 2 groups of 128 threads (sign = tid>>7); each thread handles 2 nodes.
__global__ void projYZ(const unsigned int* __restrict__ p, const float* __restrict__ x,
                       const float* __restrict__ W1p, const float* __restrict__ W1n,
                       int n) {
    __shared__ float Wp[64 * 32];
    __shared__ float Wn[64 * 32];
    for (int t = threadIdx.x; t < 64 * 32; t += blockDim.x) { Wp[t] = W1p[t]; Wn[t] = W1n[t]; }
    if (blockIdx.x == 0 && threadIdx.x == 0) {
        int is64 = 1;
        for (int i = 1; i < 256; i += 2)
            if (p[i] != 0u) { is64 = 0; break; }
        g_is64 = is64;
    }
    __syncthreads();
    int sign = threadIdx.x >> 7;
    int i0 = blockIdx.x * 256 + (threadIdx.x & 127);
    int i1 = i0 + 128;
    if (i0 >= n) return;
    bool v1 = (i1 < n);
    int i1c = v1 ? i1 : i0;

    // zero scatter targets for this thread's nodes (per sign)
    {
        const uint4 z = make_uint4(0, 0, 0, 0);
        __half* asum = sign ? g_ansum : g_apsum;
        __half* lsum = sign ? g_sumn : g_sump;
        float* cnt = sign ? g_cntn : g_cntp;
        uint4* a0z = (uint4*)(asum + (size_t)i0 * 32);
        uint4* s0z = (uint4*)(lsum + (size_t)i0 * 64);
#pragma unroll
        for (int q = 0; q < 4; q++) a0z[q] = z;
#pragma unroll
        for (int q = 0; q < 8; q++) s0z[q] = z;
        cnt[i0] = 0.f;
        if (v1) {
            uint4* a1z = (uint4*)(asum + (size_t)i1 * 32);
            uint4* s1z = (uint4*)(lsum + (size_t)i1 * 64);
#pragma unroll
            for (int q = 0; q < 4; q++) a1z[q] = z;
#pragma unroll
            for (int q = 0; q < 8; q++) s1z[q] = z;
            cnt[i1] = 0.f;
        }
    }

    const float* Ws = sign ? Wn : Wp;
    const float4* x0 = (const float4*)x + (size_t)i0 * 16;
    const float4* x1 = (const float4*)x + (size_t)i1c * 16;

    u64 a0[16], a1[16];
#pragma unroll
    for (int j = 0; j < 16; j++) { a0[j] = 0ULL; a1[j] = 0ULL; }
#pragma unroll 2
    for (int kk = 0; kk < 16; kk++) {
        float4 pv = x0[kk];
        float4 qv = x1[kk];
        int k = kk * 4;
        row_fma2n(a0, a1, Ws, k + 0, pack2(pv.x), pack2(qv.x));
        row_fma2n(a0, a1, Ws, k + 1, pack2(pv.y), pack2(qv.y));
        row_fma2n(a0, a1, Ws, k + 2, pack2(pv.z), pack2(qv.z));
        row_fma2n(a0, a1, Ws, k + 3, pack2(pv.w), pack2(qv.w));
    }
    __half* yb = sign ? g_yn : g_yp;
    uint4* yo0 = (uint4*)(yb + (size_t)i0 * 32);
#pragma unroll
    for (int q = 0; q < 4; q++) {
        float2 f0 = unpack2(a0[q * 4 + 0]), f1 = unpack2(a0[q * 4 + 1]);
        float2 f2 = unpack2(a0[q * 4 + 2]), f3 = unpack2(a0[q * 4 + 3]);
        yo0[q] = make_uint4(f2h(f0.x, f0.y), f2h(f1.x, f1.y), f2h(f2.x, f2.y), f2h(f3.x, f3.y));
    }
    if (v1) {
        uint4* yo1 = (uint4*)(yb + (size_t)i1 * 32);
#pragma unroll
        for (int q = 0; q < 4; q++) {
            float2 f0 = unpack2(a1[q * 4 + 0]), f1 = unpack2(a1[q * 4 + 1]);
            float2 f2 = unpack2(a1[q * 4 + 2]), f3 = unpack2(a1[q * 4 + 3]);
            yo1[q] = make_uint4(f2h(f0.x, f0.y), f2h(f1.x, f1.y), f2h(f2.x, f2.y), f2h(f3.x, f3.y));
        }
    }
}

// ---------------- layer-1 edge scatter (fp16, 64B rows) + counts -------------
__device__ __forceinline__ void edge1_body(const void* pe, const void* ne, int E,
                                           int is64, long long item) {
    long long e2 = item >> 2;
    int c = (int)(item & 3);
    bool pos = e2 < E;
    const void* ei = pos ? pe : ne;
    long long e = pos ? e2 : e2 - E;
    const __half* y = pos ? g_yp : g_yn;
    __half* sum = pos ? g_apsum : g_ansum;
    float* cnt = pos ? g_cntp : g_cntn;
    int s = load_idx(ei, e, is64);
    int d = load_idx(ei, (long long)E + e, is64);
    uint4 v = __ldg((const uint4*)y + (size_t)s * 4 + c);
    red_add_h8((uint4*)sum + (size_t)d * 4 + c, v);
    if (c == 0) atomicAdd(cnt + d, 1.0f);
}

__global__ void edge1(const void* __restrict__ pe, const void* __restrict__ ne, int E) {
    const int is64 = g_is64;
    long long total = (long long)E * 8;  // 2E edges * 4 items (16B each)
    long long stride = (long long)gridDim.x * blockDim.x;
    long long item = (long long)blockIdx.x * blockDim.x + threadIdx.x;
    for (; item + stride < total; item += 2 * stride) {
        edge1_body(pe, ne, E, is64, item);
        edge1_body(pe, ne, E, is64, item + stride);
    }
    if (item < total) edge1_body(pe, ne, E, is64, item);
}

// ---------------- layer-1 fused: sx = x@W1[64:128]+b; zc = tanh(sum*inv+sx) --
// 2 groups of 128 threads (sign = tid>>7); each thread handles 2 nodes.
__global__ void node1(const float* __restrict__ x,
                      const float* __restrict__ W1p, const float* __restrict__ b1p,
                      const float* __restrict__ W1n, const float* __restrict__ b1n,
                      int n) {
    __shared__ float Wp[64 * 32];
    __shared__ float Wn[64 * 32];
    for (int t = threadIdx.x; t < 64 * 32; t += blockDim.x) {
        Wp[t] = W1p[64 * 32 + t];
        Wn[t] = W1n[64 * 32 + t];
    }
    __syncthreads();
    int sign = threadIdx.x >> 7;
    int i0 = blockIdx.x * 256 + (threadIdx.x & 127);
    int i1 = i0 + 128;
    if (i0 >= n) return;
    bool v1 = (i1 < n);
    int i1c = v1 ? i1 : i0;

    const float* Ws = sign ? Wn : Wp;
    const float4* x0 = (const float4*)x + (size_t)i0 * 16;
    const float4* x1 = (const float4*)x + (size_t)i1c * 16;

    u64 a0[16], a1[16];
#pragma unroll
    for (int j = 0; j < 16; j++) { a0[j] = 0ULL; a1[j] = 0ULL; }
#pragma unroll 2
    for (int kk = 0; kk < 16; kk++) {
        float4 pv = x0[kk];
        float4 qv = x1[kk];
        int k = kk * 4;
        row_fma2n(a0, a1, Ws, k + 0, pack2(pv.x), pack2(qv.x));
        row_fma2n(a0, a1, Ws, k + 1, pack2(pv.y), pack2(qv.y));
        row_fma2n(a0, a1, Ws, k + 2, pack2(pv.z), pack2(qv.z));
        row_fma2n(a0, a1, Ws, k + 3, pack2(pv.w), pack2(qv.w));
    }

    const float* cnt = sign ? g_cntn : g_cntp;
    const __half* asum = sign ? g_ansum : g_apsum;
    const float2* bb = (const float2*)(sign ? b1n : b1p);
    float inv0 = 1.f / fmaxf(cnt[i0], 1.f);
    float inv1 = 1.f / fmaxf(cnt[i1c], 1.f);
    int ho = sign ? 4 : 0;

    // node i0
    {
        const uint4* ar = (const uint4*)(asum + (size_t)i0 * 32);
        uint4* zo = (uint4*)g_zc + (size_t)i0 * 8 + ho;
#pragma unroll
        for (int q = 0; q < 4; q++) {
            uint4 av = __ldg(ar + q);
            u32 w[4];
#pragma unroll
            for (int j = 0; j < 4; j++) {
                float2 s = unpack2(a0[q * 4 + j]);
                float2 b = __ldg(bb + q * 4 + j);
                float2 m = h2f(j == 0 ? av.x : (j == 1 ? av.y : (j == 2 ? av.z : av.w)));
                w[j] = f2h(tanhf(fmaf(m.x, inv0, s.x + b.x)),
                           tanhf(fmaf(m.y, inv0, s.y + b.y)));
            }
            zo[q] = make_uint4(w[0], w[1], w[2], w[3]);
        }
    }
    // node i1
    if (v1) {
        const uint4* ar = (const uint4*)(asum + (size_t)i1 * 32);
        uint4* zo = (uint4*)g_zc + (size_t)i1 * 8 + ho;
#pragma unroll
        for (int q = 0; q < 4; q++) {
            uint4 av = __ldg(ar + q);
            u32 w[4];
#pragma unroll
            for (int j = 0; j < 4; j++) {
                float2 s = unpack2(a1[q * 4 + j]);
                float2 b = __ldg(bb + q * 4 + j);
                float2 m = h2f(j == 0 ? av.x : (j == 1 ? av.y : (j == 2 ? av.z : av.w)));
                w[j] = f2h(tanhf(fmaf(m.x, inv1, s.x + b.x)),
                           tanhf(fmaf(m.y, inv1, s.y + b.y)));
            }
            zo[q] = make_uint4(w[0], w[1], w[2], w[3]);
        }
    }
}

// ---------------- layer-2 edge scatter (fp16 zc rows, 128B) ------------------
__device__ __forceinline__ void edge2_body(const void* pe, const void* ne, int E,
                                           int is64, long long item) {
    long long e2 = item >> 3;
    int c = (int)(item & 7);
    bool pos = e2 < E;
    const void* ei = pos ? pe : ne;
    long long e = pos ? e2 : e2 - E;
    __half* sum = pos ? g_sump : g_sumn;
    int s = load_idx(ei, e, is64);
    int d = load_idx(ei, (long long)E + e, is64);
    uint4 v = __ldg((const uint4*)g_zc + (size_t)s * 8 + c);
    red_add_h8((uint4*)sum + (size_t)d * 8 + c, v);
}

__global__ void edge2(const void* __restrict__ pe, const void* __restrict__ ne, int E) {
    const int is64 = g_is64;
    long long total = (long long)E * 16;  // 2E edges * 8 items (16B each)
    long long stride = (long long)gridDim.x * blockDim.x;
    long long item = (long long)blockIdx.x * blockDim.x + threadIdx.x;
    for (; item + stride < total; item += 2 * stride) {
        edge2_body(pe, ne, E, is64, item);
        edge2_body(pe, ne, E, is64, item + stride);
    }
    if (item < total) edge2_body(pe, ne, E, is64, item);
}

// ---------------- layer-2 dual-node GEMM section ------------------------------
__device__ __forceinline__ void gemm_sec2n(u64 a0[16], u64 a1[16], const float* Ws,
                                           int kbase, const uint4* s0p, const uint4* s1p,
                                           float sc0, float sc1) {
#pragma unroll
    for (int q = 0; q < 4; q++) {
        uint4 u0 = __ldg(s0p + q);
        uint4 u1 = __ldg(s1p + q);
        int k = kbase + q * 8;
        float2 f0, f1;
        f0 = h2f(u0.x); f1 = h2f(u1.x);
        row_fma2n(a0, a1, Ws, k + 0, pack2(f0.x * sc0), pack2(f1.x * sc1));
        row_fma2n(a0, a1, Ws, k + 1, pack2(f0.y * sc0), pack2(f1.y * sc1));
        f0 = h2f(u0.y); f1 = h2f(u1.y);
        row_fma2n(a0, a1, Ws, k + 2, pack2(f0.x * sc0), pack2(f1.x * sc1));
        row_fma2n(a0, a1, Ws, k + 3, pack2(f0.y * sc0), pack2(f1.y * sc1));
        f0 = h2f(u0.z); f1 = h2f(u1.z);
        row_fma2n(a0, a1, Ws, k + 4, pack2(f0.x * sc0), pack2(f1.x * sc1));
        row_fma2n(a0, a1, Ws, k + 5, pack2(f0.y * sc0), pack2(f1.y * sc1));
        f0 = h2f(u0.w); f1 = h2f(u1.w);
        row_fma2n(a0, a1, Ws, k + 6, pack2(f0.x * sc0), pack2(f1.x * sc1));
        row_fma2n(a0, a1, Ws, k + 7, pack2(f0.y * sc0), pack2(f1.y * sc1));
    }
}

// ---------------- layer-2 node GEMM -> output (2-node blocked) ----------------
// 2 groups of 128 threads: sign = tid>>7; each thread does nodes i and i+128.
__global__ void node_l2(const float* __restrict__ W2p, const float* __restrict__ b2p,
                        const float* __restrict__ W2n, const float* __restrict__ b2n,
                        float* __restrict__ out, int n) {
    __shared__ float Wp[96 * 32];
    __shared__ float Wn[96 * 32];
    for (int t = threadIdx.x; t < 96 * 32; t += blockDim.x) { Wp[t] = W2p[t]; Wn[t] = W2n[t]; }
    __syncthreads();
    int sign = threadIdx.x >> 7;
    int i0 = blockIdx.x * 256 + (threadIdx.x & 127);
    int i1 = i0 + 128;
    if (i0 >= n) return;
    bool v1 = (i1 < n);
    int i1c = v1 ? i1 : i0;

    float invp0 = 1.f / fmaxf(g_cntp[i0], 1.f);
    float invn0 = 1.f / fmaxf(g_cntn[i0], 1.f);
    float invp1 = 1.f / fmaxf(g_cntp[i1c], 1.f);
    float invn1 = 1.f / fmaxf(g_cntn[i1c], 1.f);

    int ho = sign ? 4 : 0;
    // pos sign: [szpp*invp, sznn*invn, zp];  neg sign: [sznp*invp, szpn*invn, zn]
    const uint4* s0a = (const uint4*)g_sump + (size_t)i0 * 8 + ho;
    const uint4* s1a = (const uint4*)g_sumn + (size_t)i0 * 8 + (4 - ho);
    const uint4* s2a = (const uint4*)g_zc   + (size_t)i0 * 8 + ho;
    const uint4* s0b = (const uint4*)g_sump + (size_t)i1c * 8 + ho;
    const uint4* s1b = (const uint4*)g_sumn + (size_t)i1c * 8 + (4 - ho);
    const uint4* s2b = (const uint4*)g_zc   + (size_t)i1c * 8 + ho;
    const float* Ws = sign ? Wn : Wp;

    u64 a0[16], a1[16];
#pragma unroll
    for (int j = 0; j < 16; j++) { a0[j] = 0ULL; a1[j] = 0ULL; }
    gemm_sec2n(a0, a1, Ws, 0,  s0a, s0b, invp0, invp1);
    gemm_sec2n(a0, a1, Ws, 32, s1a, s1b, invn0, invn1);
    gemm_sec2n(a0, a1, Ws, 64, s2a, s2b, 1.0f, 1.0f);

    const float2* bb = (const float2*)(sign ? b2n : b2p);
    float2* o0 = (float2*)(out + (size_t)i0 * 64 + (sign ? 32 : 0));
    float2* o1 = (float2*)(out + (size_t)i1 * 64 + (sign ? 32 : 0));
#pragma unroll
    for (int j = 0; j < 16; j++) {
        float2 b = __ldg(bb + j);
        float2 f = unpack2(a0[j]);
        o0[j] = make_float2(tanhf(f.x + b.x), tanhf(f.y + b.y));
        if (v1) {
            f = unpack2(a1[j]);
            o1[j] = make_float2(tanhf(f.x + b.x), tanhf(f.y + b.y));
        }
    }
}

// ---------------- launch ------------------------------------------------------
extern "C" void kernel_launch(void* const* d_in, const int* in_sizes, int n_in,
                              void* d_out, int out_size) {
    const float* x   = (const float*)d_in[0];
    const float* W1p = (const float*)d_in[1];
    const float* b1p = (const float*)d_in[2];
    const float* W1n = (const float*)d_in[3];
    const float* b1n = (const float*)d_in[4];
    const float* W2p = (const float*)d_in[5];
    const float* b2p = (const float*)d_in[6];
    const float* W2n = (const float*)d_in[7];
    const float* b2n = (const float*)d_in[8];
    const void* pe = d_in[9];
    const void* ne = d_in[10];

    int n = in_sizes[0] / 64;
    int E = in_sizes[9] / 2;
    float* out = (float*)d_out;

    projYZ<<<(n + 255) / 256, 256>>>((const unsigned int*)pe, x, W1p, W1n, n);
    edge1<<<4736, 256>>>(pe, ne, E);
    node1<<<(n + 255) / 256, 256>>>(x, W1p, b1p, W1n, b1n, n);
    edge2<<<4736, 256>>>(pe, ne, E);
    node_l2<<<(n + 255) / 256, 256>>>(W2p, b2p, W2n, b2n, out, n);
}